// round 9
// baseline (speedup 1.0000x reference)
#include <cuda_runtime.h>
#include <cstdint>

#define BETA_C (8.0f / 3.0f)

// ---------------- scalar step (tail kernel only) ----------------
__device__ __forceinline__ void lorenz_step(float yin0, float yin1, float yin2,
                                            float& o0, float& o1, float& o2) {
    const float h  = 0.01f;
    const float c1 = 0.5f * h;
    const float c2 = h * h / 6.0f;
    const float c3 = h * h * h / 8.0f;
    const float c4 = h * h * h / 24.0f;

    float y0 = 10.0f * yin0, y1 = 10.0f * yin1, y2 = 10.0f * yin2;
    float f0 = 10.0f * y1 - 10.0f * y0;
    float f1 = 28.0f * y0 - y0 * y2 - y1;
    float f2 = y0 * y1 - BETA_C * y2;
    float j00 = 28.0f - y2;
    float dff0 = 10.0f * f1 - 10.0f * f0;
    float dff1 = j00 * f0 - f1 - y0 * f2;
    float dff2 = y1 * f0 + y0 * f1 - BETA_C * f2;
    float dfdff0 = 10.0f * dff1 - 10.0f * dff0;
    float dfdff1 = j00 * dff0 - dff1 - y0 * dff2;
    float dfdff2 = y1 * dff0 + y0 * dff1 - BETA_C * dff2;
    float ddfff1 = -2.0f * f0 * f2;
    float ddfff2 =  2.0f * f0 * f1;
    float ddfdfff1 = -dff0 * f2 - dff2 * f0;
    float ddfdfff2 =  dff0 * f1 + dff1 * f0;
    float dfddfff0 = 10.0f * ddfff1;
    float dfddfff1 = -ddfff1 - y0 * ddfff2;
    float dfddfff2 = y0 * f1 - BETA_C * ddfff2;
    float dfdfdff0 = 10.0f * dfdff1 - 10.0f * dfdff0;
    float dfdfdff1 = j00 * dfdff0 - dfdff1 - y0 * dfdff2;
    float dfdfdff2 = y1 * dfdff0 + y0 * dfdff1 - BETA_C * dfdff2;
    o0 = (f0 + c1 * dff0 + c2 * dfdff0 + c4 * (dfddfff0 + dfdfdff0)) * 0.1f;
    o1 = (f1 + c1 * dff1 + c2 * (ddfff1 + dfdff1)
             + c3 * ddfdfff1 + c4 * (dfddfff1 + dfdfdff1)) * 0.1f;
    o2 = (f2 + c1 * dff2 + c2 * (ddfff2 + dfdff2)
             + c3 * ddfdfff2 + c4 * (dfddfff2 + dfdfdff2)) * 0.1f;
}

// ---------------- packed f32x2 primitives ----------------
typedef unsigned long long u64;

__device__ __forceinline__ u64 f2pk(float lo, float hi) {
    u64 d;
    asm("mov.b64 %0, {%1, %2};" : "=l"(d)
        : "r"(__float_as_uint(lo)), "r"(__float_as_uint(hi)));
    return d;
}
__device__ __forceinline__ void f2up(u64 v, float& lo, float& hi) {
    uint32_t a, b;
    asm("mov.b64 {%0, %1}, %2;" : "=r"(a), "=r"(b) : "l"(v));
    lo = __uint_as_float(a); hi = __uint_as_float(b);
}
__device__ __forceinline__ u64 f2mul(u64 a, u64 b) {
    u64 d; asm("mul.rn.f32x2 %0, %1, %2;" : "=l"(d) : "l"(a), "l"(b)); return d;
}
__device__ __forceinline__ u64 f2add(u64 a, u64 b) {
    u64 d; asm("add.rn.f32x2 %0, %1, %2;" : "=l"(d) : "l"(a), "l"(b)); return d;
}
__device__ __forceinline__ u64 f2fma(u64 a, u64 b, u64 c) {
    u64 d; asm("fma.rn.f32x2 %0, %1, %2, %3;" : "=l"(d) : "l"(a), "l"(b), "l"(c)); return d;
}

struct PkConsts {
    u64 K10, K28, KnB, Kn2, K2, Kn1, K01, Kc1, Kc2, Kc3, Knc3, Kc4;
};
__device__ __forceinline__ PkConsts make_consts() {
    const float h = 0.01f;
    PkConsts k;
    k.K10 = f2pk(10.0f, 10.0f);
    k.K28 = f2pk(28.0f, 28.0f);
    k.KnB = f2pk(-BETA_C, -BETA_C);
    k.Kn2 = f2pk(-2.0f, -2.0f);
    k.K2  = f2pk(2.0f, 2.0f);
    k.Kn1 = f2pk(-1.0f, -1.0f);
    k.K01 = f2pk(0.1f, 0.1f);
    k.Kc1 = f2pk(0.5f * h, 0.5f * h);
    k.Kc2 = f2pk(h * h / 6.0f, h * h / 6.0f);
    k.Kc3 = f2pk(h * h * h / 8.0f, h * h * h / 8.0f);
    k.Knc3 = f2pk(-h * h * h / 8.0f, -h * h * h / 8.0f);
    k.Kc4 = f2pk(h * h * h / 24.0f, h * h * h / 24.0f);
    return k;
}

#define F2SUB(a, b) f2fma((b), k.Kn1, (a))

// Packed Lorenz Taylor step: TWO independent triples (lo/hi halves).
__device__ __forceinline__ void lorenz2(const PkConsts& k,
                                        u64& x0, u64& x1, u64& x2) {
    u64 y0 = f2mul(k.K10, x0);
    u64 y1 = f2mul(k.K10, x1);
    u64 y2 = f2mul(k.K10, x2);

    u64 f0 = f2mul(k.K10, F2SUB(y1, y0));
    u64 j  = F2SUB(k.K28, y2);
    u64 f1 = F2SUB(f2mul(y0, j), y1);
    u64 f2v = f2fma(y0, y1, f2mul(k.KnB, y2));

    u64 dff0 = f2mul(k.K10, F2SUB(f1, f0));
    u64 dff1 = F2SUB(f2mul(j, f0), f2fma(y0, f2v, f1));
    u64 dff2 = f2fma(y1, f0, f2fma(y0, f1, f2mul(k.KnB, f2v)));

    u64 dfdff0 = f2mul(k.K10, F2SUB(dff1, dff0));
    u64 dfdff1 = F2SUB(f2mul(j, dff0), f2fma(y0, dff2, dff1));
    u64 dfdff2 = f2fma(y1, dff0, f2fma(y0, dff1, f2mul(k.KnB, dff2)));

    u64 ddfff1 = f2mul(k.Kn2, f2mul(f0, f2v));
    u64 ddfff2 = f2mul(k.K2,  f2mul(f0, f1));

    u64 nddfdfff1 = f2fma(dff0, f2v, f2mul(dff2, f0));   // = -ddfdfff1
    u64 ddfdfff2  = f2fma(dff0, f1,  f2mul(dff1, f0));

    u64 dfddfff0  = f2mul(k.K10, ddfff1);
    u64 ndfddfff1 = f2fma(y0, ddfff2, ddfff1);           // = -dfddfff1
    u64 dfddfff2  = f2fma(y0, f1, f2mul(k.KnB, ddfff2)); // ref quirk

    u64 dfdfdff0 = f2mul(k.K10, F2SUB(dfdff1, dfdff0));
    u64 dfdfdff1 = F2SUB(f2mul(j, dfdff0), f2fma(y0, dfdff2, dfdff1));
    u64 dfdfdff2 = f2fma(y1, dfdff0, f2fma(y0, dfdff1, f2mul(k.KnB, dfdff2)));

    u64 acc = f2fma(k.Kc1, dff0, f0);
    acc = f2fma(k.Kc2, dfdff0, acc);
    acc = f2fma(k.Kc4, f2add(dfddfff0, dfdfdff0), acc);
    x0 = f2mul(k.K01, acc);

    acc = f2fma(k.Kc1, dff1, f1);
    acc = f2fma(k.Kc2, f2add(ddfff1, dfdff1), acc);
    acc = f2fma(k.Knc3, nddfdfff1, acc);
    acc = f2fma(k.Kc4, F2SUB(dfdfdff1, ndfddfff1), acc);
    x1 = f2mul(k.K01, acc);

    acc = f2fma(k.Kc1, dff2, f2v);
    acc = f2fma(k.Kc2, f2add(ddfff2, dfdff2), acc);
    acc = f2fma(k.Kc3, ddfdfff2, acc);
    acc = f2fma(k.Kc4, f2add(dfddfff2, dfdfdff2), acc);
    x2 = f2mul(k.K01, acc);
}

// Shuffle-transpose kernel. Each warp handles 192 consecutive floats
// (2 chunks of 96 = 2x32 triples). Coalesced LDG.32/STG.32 only; the
// AoS<->triple transpose is done with 3 SHFL + selects per direction
// (gcd(3,32)=1 -> each round's lane map is a bijection). Zero smem,
// zero barriers, zero redundant compute.
__global__ void __launch_bounds__(256) IE_LS_kernel(
    const float* __restrict__ in, float* __restrict__ out) {
    const int lane = threadIdx.x & 31;
    const int warpg = blockIdx.x * 8 + (threadIdx.x >> 5);
    const long long base = (long long)warpg * 192;

    // Transpose constants (same t/i drive gather send-select and scatter):
    //   t_j = (11*(lane-j)) & 31,  i_j = (3*t_j + j) >> 5
    const int t0 = (11 * (lane - 0)) & 31;
    const int t1 = (11 * (lane - 1)) & 31;
    const int t2 = (11 * (lane - 2)) & 31;
    const int i0 = (3 * t0 + 0) >> 5;
    const int i1 = (3 * t1 + 1) >> 5;
    const int i2 = (3 * t2 + 2) >> 5;
    const int g0 = (3 * lane + 0) & 31;   // gather src lanes
    const int g1 = (3 * lane + 1) & 31;
    const int g2 = (3 * lane + 2) & 31;

    // Coalesced loads: chunk A at base, chunk B at base+96. Pack A/B early.
    u64 p0 = f2pk(in[base + lane],      in[base + 96 + lane]);
    u64 p1 = f2pk(in[base + 32 + lane], in[base + 128 + lane]);
    u64 p2 = f2pk(in[base + 64 + lane], in[base + 160 + lane]);

    const unsigned m = 0xFFFFFFFFu;

    // Gather: lane ends with packed triple (A-triple lane, B-triple lane).
    u64 s0 = (i0 == 0) ? p0 : (i0 == 1) ? p1 : p2;
    u64 s1 = (i1 == 0) ? p0 : (i1 == 1) ? p1 : p2;
    u64 s2 = (i2 == 0) ? p0 : (i2 == 1) ? p1 : p2;
    u64 x0 = __shfl_sync(m, s0, g0);
    u64 x1 = __shfl_sync(m, s1, g1);
    u64 x2 = __shfl_sync(m, s2, g2);

    const PkConsts k = make_consts();
    lorenz2(k, x0, x1, x2);

    // Scatter: round c, every lane sends o_c; receiver lane pulls from t_c
    // and places into coalesced register i_c.
    u64 v0 = __shfl_sync(m, x0, t0);
    u64 v1 = __shfl_sync(m, x1, t1);
    u64 v2 = __shfl_sync(m, x2, t2);
    u64 q0 = (i0 == 0) ? v0 : (i1 == 0) ? v1 : v2;
    u64 q1 = (i0 == 1) ? v0 : (i1 == 1) ? v1 : v2;
    u64 q2 = (i0 == 2) ? v0 : (i1 == 2) ? v1 : v2;

    float lo, hi;
    f2up(q0, lo, hi); out[base + lane]       = lo; out[base + 96 + lane]  = hi;
    f2up(q1, lo, hi); out[base + 32 + lane]  = lo; out[base + 128 + lane] = hi;
    f2up(q2, lo, hi); out[base + 64 + lane]  = lo; out[base + 160 + lane] = hi;
}

// Tail kernel for leftover triples (not hit for the bench shape).
__global__ void IE_LS_tail_kernel(const float* __restrict__ in,
                                  float* __restrict__ out,
                                  int start_triple, int n_triples) {
    int t = start_triple + blockIdx.x * blockDim.x + threadIdx.x;
    if (t >= n_triples) return;
    float o0, o1, o2;
    lorenz_step(in[3 * t], in[3 * t + 1], in[3 * t + 2], o0, o1, o2);
    out[3 * t] = o0; out[3 * t + 1] = o1; out[3 * t + 2] = o2;
}

extern "C" void kernel_launch(void* const* d_in, const int* in_sizes, int n_in,
                              void* d_out, int out_size) {
    const float* in = (const float*)d_in[0];
    float* out = (float*)d_out;
    int n_elems = in_sizes[0];             // 12582912 = 4194304 * 3
    int n_triples = n_elems / 3;
    int n_warps = n_elems / 192;           // 192 floats (64 triples) per warp
    int n_blocks = n_warps / 8;            // 8 warps per 256-thread block

    if (n_blocks > 0) {
        IE_LS_kernel<<<n_blocks, 256>>>(in, out);
    }
    int done = n_blocks * 8 * 64;          // triples covered by main kernel
    int rem = n_triples - done;
    if (rem > 0) {
        IE_LS_tail_kernel<<<(rem + 255) / 256, 256>>>(in, out, done, n_triples);
    }
}

// round 10
// speedup vs baseline: 1.0918x; 1.0918x over previous
#include <cuda_runtime.h>
#include <cstdint>

#define BETA_C (8.0f / 3.0f)

// ---------------- scalar step (tail kernel only) ----------------
__device__ __forceinline__ void lorenz_step(float yin0, float yin1, float yin2,
                                            float& o0, float& o1, float& o2) {
    const float h  = 0.01f;
    const float c1 = 0.5f * h;
    const float c2 = h * h / 6.0f;
    const float c3 = h * h * h / 8.0f;
    const float c4 = h * h * h / 24.0f;

    float y0 = 10.0f * yin0, y1 = 10.0f * yin1, y2 = 10.0f * yin2;
    float f0 = 10.0f * y1 - 10.0f * y0;
    float f1 = 28.0f * y0 - y0 * y2 - y1;
    float f2 = y0 * y1 - BETA_C * y2;
    float j00 = 28.0f - y2;
    float dff0 = 10.0f * f1 - 10.0f * f0;
    float dff1 = j00 * f0 - f1 - y0 * f2;
    float dff2 = y1 * f0 + y0 * f1 - BETA_C * f2;
    float dfdff0 = 10.0f * dff1 - 10.0f * dff0;
    float dfdff1 = j00 * dff0 - dff1 - y0 * dff2;
    float dfdff2 = y1 * dff0 + y0 * dff1 - BETA_C * dff2;
    float ddfff1 = -2.0f * f0 * f2;
    float ddfff2 =  2.0f * f0 * f1;
    float ddfdfff1 = -dff0 * f2 - dff2 * f0;
    float ddfdfff2 =  dff0 * f1 + dff1 * f0;
    float dfddfff0 = 10.0f * ddfff1;
    float dfddfff1 = -ddfff1 - y0 * ddfff2;
    float dfddfff2 = y0 * f1 - BETA_C * ddfff2;
    float dfdfdff0 = 10.0f * dfdff1 - 10.0f * dfdff0;
    float dfdfdff1 = j00 * dfdff0 - dfdff1 - y0 * dfdff2;
    float dfdfdff2 = y1 * dfdff0 + y0 * dfdff1 - BETA_C * dfdff2;
    o0 = (f0 + c1 * dff0 + c2 * dfdff0 + c4 * (dfddfff0 + dfdfdff0)) * 0.1f;
    o1 = (f1 + c1 * dff1 + c2 * (ddfff1 + dfdff1)
             + c3 * ddfdfff1 + c4 * (dfddfff1 + dfdfdff1)) * 0.1f;
    o2 = (f2 + c1 * dff2 + c2 * (ddfff2 + dfdff2)
             + c3 * ddfdfff2 + c4 * (dfddfff2 + dfdfdff2)) * 0.1f;
}

// ---------------- packed f32x2 primitives ----------------
typedef unsigned long long u64;

__device__ __forceinline__ u64 f2pk(float lo, float hi) {
    u64 d;
    asm("mov.b64 %0, {%1, %2};" : "=l"(d)
        : "r"(__float_as_uint(lo)), "r"(__float_as_uint(hi)));
    return d;
}
__device__ __forceinline__ void f2up(u64 v, float& lo, float& hi) {
    uint32_t a, b;
    asm("mov.b64 {%0, %1}, %2;" : "=r"(a), "=r"(b) : "l"(v));
    lo = __uint_as_float(a); hi = __uint_as_float(b);
}
__device__ __forceinline__ u64 f2mul(u64 a, u64 b) {
    u64 d; asm("mul.rn.f32x2 %0, %1, %2;" : "=l"(d) : "l"(a), "l"(b)); return d;
}
__device__ __forceinline__ u64 f2add(u64 a, u64 b) {
    u64 d; asm("add.rn.f32x2 %0, %1, %2;" : "=l"(d) : "l"(a), "l"(b)); return d;
}
__device__ __forceinline__ u64 f2fma(u64 a, u64 b, u64 c) {
    u64 d; asm("fma.rn.f32x2 %0, %1, %2, %3;" : "=l"(d) : "l"(a), "l"(b), "l"(c)); return d;
}

struct PkConsts {
    u64 K10, K28, KnB, Kn2, K2, Kn1, K01, Kc1, Kc2, Kc3, Knc3, Kc4;
};
__device__ __forceinline__ PkConsts make_consts() {
    const float h = 0.01f;
    PkConsts k;
    k.K10 = f2pk(10.0f, 10.0f);
    k.K28 = f2pk(28.0f, 28.0f);
    k.KnB = f2pk(-BETA_C, -BETA_C);
    k.Kn2 = f2pk(-2.0f, -2.0f);
    k.K2  = f2pk(2.0f, 2.0f);
    k.Kn1 = f2pk(-1.0f, -1.0f);
    k.K01 = f2pk(0.1f, 0.1f);
    k.Kc1 = f2pk(0.5f * h, 0.5f * h);
    k.Kc2 = f2pk(h * h / 6.0f, h * h / 6.0f);
    k.Kc3 = f2pk(h * h * h / 8.0f, h * h * h / 8.0f);
    k.Knc3 = f2pk(-h * h * h / 8.0f, -h * h * h / 8.0f);
    k.Kc4 = f2pk(h * h * h / 24.0f, h * h * h / 24.0f);
    return k;
}

#define F2SUB(a, b) f2fma((b), k.Kn1, (a))

// Packed Lorenz Taylor step: TWO independent triples (lo/hi halves).
__device__ __forceinline__ void lorenz2(const PkConsts& k,
                                        u64& x0, u64& x1, u64& x2) {
    u64 y0 = f2mul(k.K10, x0);
    u64 y1 = f2mul(k.K10, x1);
    u64 y2 = f2mul(k.K10, x2);

    u64 f0 = f2mul(k.K10, F2SUB(y1, y0));
    u64 j  = F2SUB(k.K28, y2);
    u64 f1 = F2SUB(f2mul(y0, j), y1);
    u64 f2v = f2fma(y0, y1, f2mul(k.KnB, y2));

    u64 dff0 = f2mul(k.K10, F2SUB(f1, f0));
    u64 dff1 = F2SUB(f2mul(j, f0), f2fma(y0, f2v, f1));
    u64 dff2 = f2fma(y1, f0, f2fma(y0, f1, f2mul(k.KnB, f2v)));

    u64 dfdff0 = f2mul(k.K10, F2SUB(dff1, dff0));
    u64 dfdff1 = F2SUB(f2mul(j, dff0), f2fma(y0, dff2, dff1));
    u64 dfdff2 = f2fma(y1, dff0, f2fma(y0, dff1, f2mul(k.KnB, dff2)));

    u64 ddfff1 = f2mul(k.Kn2, f2mul(f0, f2v));
    u64 ddfff2 = f2mul(k.K2,  f2mul(f0, f1));

    u64 nddfdfff1 = f2fma(dff0, f2v, f2mul(dff2, f0));   // = -ddfdfff1
    u64 ddfdfff2  = f2fma(dff0, f1,  f2mul(dff1, f0));

    u64 dfddfff0  = f2mul(k.K10, ddfff1);
    u64 ndfddfff1 = f2fma(y0, ddfff2, ddfff1);           // = -dfddfff1
    u64 dfddfff2  = f2fma(y0, f1, f2mul(k.KnB, ddfff2)); // ref quirk

    u64 dfdfdff0 = f2mul(k.K10, F2SUB(dfdff1, dfdff0));
    u64 dfdfdff1 = F2SUB(f2mul(j, dfdff0), f2fma(y0, dfdff2, dfdff1));
    u64 dfdfdff2 = f2fma(y1, dfdff0, f2fma(y0, dfdff1, f2mul(k.KnB, dfdff2)));

    u64 acc = f2fma(k.Kc1, dff0, f0);
    acc = f2fma(k.Kc2, dfdff0, acc);
    acc = f2fma(k.Kc4, f2add(dfddfff0, dfdfdff0), acc);
    x0 = f2mul(k.K01, acc);

    acc = f2fma(k.Kc1, dff1, f1);
    acc = f2fma(k.Kc2, f2add(ddfff1, dfdff1), acc);
    acc = f2fma(k.Knc3, nddfdfff1, acc);
    acc = f2fma(k.Kc4, F2SUB(dfdfdff1, ndfddfff1), acc);
    x1 = f2mul(k.K01, acc);

    acc = f2fma(k.Kc1, dff2, f2v);
    acc = f2fma(k.Kc2, f2add(ddfff2, dfdff2), acc);
    acc = f2fma(k.Kc3, ddfdfff2, acc);
    acc = f2fma(k.Kc4, f2add(dfddfff2, dfdfdff2), acc);
    x2 = f2mul(k.K01, acc);
}

// Pack 3 float4s (= 4 consecutive triples) into two packed triple-pairs.
__device__ __forceinline__ void pack3(const float4& a, const float4& b,
                                      const float4& c, u64* u, u64* v) {
    u[0] = f2pk(a.x, a.w);
    u[1] = f2pk(a.y, b.x);
    u[2] = f2pk(a.z, b.y);
    v[0] = f2pk(b.z, c.y);
    v[1] = f2pk(b.w, c.z);
    v[2] = f2pk(c.x, c.w);
}
__device__ __forceinline__ void unpack3(const u64* u, const u64* v,
                                        float4& a, float4& b, float4& c) {
    f2up(u[0], a.x, a.w);
    f2up(u[1], a.y, b.x);
    f2up(u[2], a.z, b.y);
    f2up(v[0], b.z, c.y);
    f2up(v[1], b.w, c.z);
    f2up(v[2], c.x, c.w);
}

// Warp-autonomous double tile: each warp owns 192 float4s (256 triples) of
// smem; each thread handles 8 triples. 6 front-batched LDG.128 per thread
// (3 KB in flight per warp) to maximize MLP; smem does the AoS<->triple
// transpose (48B-stride LDS.128, conflict-free; chunk offset 1536B = 0 mod
// 128 so chunk B has the identical bank pattern). f32x2 packed math.
__global__ void IE_LS_kernel(const float4* __restrict__ in,
                             float4* __restrict__ out) {
    __shared__ float4 s[1536];   // 8 warps * 192

    const int lane = threadIdx.x & 31;
    const int warp = threadIdx.x >> 5;
    float4* sw = s + warp * 192;
    const long long gbase = (long long)blockIdx.x * 1536 + warp * 192;

    // Phase A: 6 coalesced LDG.128 -> warp-local smem
#pragma unroll
    for (int kk = 0; kk < 6; kk++)
        sw[lane + 32 * kk] = in[gbase + lane + 32 * kk];
    __syncwarp();

    // Phase B: chunk A = sw[0..95], chunk B = sw[96..191].
    float4 a0 = sw[3 * lane + 0];
    float4 a1 = sw[3 * lane + 1];
    float4 a2 = sw[3 * lane + 2];
    float4 b0 = sw[96 + 3 * lane + 0];
    float4 b1 = sw[96 + 3 * lane + 1];
    float4 b2 = sw[96 + 3 * lane + 2];

    const PkConsts k = make_consts();

    u64 X[4][3];
    pack3(a0, a1, a2, X[0], X[1]);
    pack3(b0, b1, b2, X[2], X[3]);

#pragma unroll
    for (int q = 0; q < 4; q++)
        lorenz2(k, X[q][0], X[q][1], X[q][2]);

    unpack3(X[0], X[1], a0, a1, a2);
    unpack3(X[2], X[3], b0, b1, b2);

    sw[3 * lane + 0] = a0;
    sw[3 * lane + 1] = a1;
    sw[3 * lane + 2] = a2;
    sw[96 + 3 * lane + 0] = b0;
    sw[96 + 3 * lane + 1] = b1;
    sw[96 + 3 * lane + 2] = b2;
    __syncwarp();

    // Phase C: 6 coalesced STG.128
#pragma unroll
    for (int kk = 0; kk < 6; kk++)
        out[gbase + lane + 32 * kk] = sw[lane + 32 * kk];
}

// Tail kernel for leftover triples (not hit for the bench shape).
__global__ void IE_LS_tail_kernel(const float* __restrict__ in,
                                  float* __restrict__ out,
                                  int start_triple, int n_triples) {
    int t = start_triple + blockIdx.x * blockDim.x + threadIdx.x;
    if (t >= n_triples) return;
    float o0, o1, o2;
    lorenz_step(in[3 * t], in[3 * t + 1], in[3 * t + 2], o0, o1, o2);
    out[3 * t] = o0; out[3 * t + 1] = o1; out[3 * t + 2] = o2;
}

extern "C" void kernel_launch(void* const* d_in, const int* in_sizes, int n_in,
                              void* d_out, int out_size) {
    const float* in = (const float*)d_in[0];
    float* out = (float*)d_out;
    int n_elems = in_sizes[0];             // 12582912 = 4194304 * 3
    int n_triples = n_elems / 3;
    int n_blocks = n_elems / 6144;         // 6144 floats (2048 triples) per block

    if (n_blocks > 0) {
        IE_LS_kernel<<<n_blocks, 256>>>((const float4*)in, (float4*)out);
    }
    int done = n_blocks * 2048;
    int rem = n_triples - done;
    if (rem > 0) {
        IE_LS_tail_kernel<<<(rem + 255) / 256, 256>>>(in, out, done, n_triples);
    }
}

// round 11
// speedup vs baseline: 1.1637x; 1.0658x over previous
#include <cuda_runtime.h>
#include <cstdint>

#define BETA_C (8.0f / 3.0f)

__device__ __forceinline__ void lorenz_step(float yin0, float yin1, float yin2,
                                            float& o0, float& o1, float& o2) {
    const float h  = 0.01f;
    const float c1 = 0.5f * h;            // a0*h
    const float c2 = h * h / 6.0f;        // a1*h^2 == a2*h^2
    const float c3 = h * h * h / 8.0f;    // a4*h^3 (=3/24)
    const float c4 = h * h * h / 24.0f;   // a5*h^3 == a6*h^3

    float y0 = 10.0f * yin0, y1 = 10.0f * yin1, y2 = 10.0f * yin2;

    float f0 = 10.0f * y1 - 10.0f * y0;
    float f1 = 28.0f * y0 - y0 * y2 - y1;
    float f2 = y0 * y1 - BETA_C * y2;

    float j00 = 28.0f - y2;

    float dff0 = 10.0f * f1 - 10.0f * f0;
    float dff1 = j00 * f0 - f1 - y0 * f2;
    float dff2 = y1 * f0 + y0 * f1 - BETA_C * f2;

    float dfdff0 = 10.0f * dff1 - 10.0f * dff0;
    float dfdff1 = j00 * dff0 - dff1 - y0 * dff2;
    float dfdff2 = y1 * dff0 + y0 * dff1 - BETA_C * dff2;

    float ddfff1 = -2.0f * f0 * f2;
    float ddfff2 =  2.0f * f0 * f1;

    float ddfdfff1 = -dff0 * f2 - dff2 * f0;
    float ddfdfff2 =  dff0 * f1 + dff1 * f0;

    float dfddfff0 = 10.0f * ddfff1;
    float dfddfff1 = -ddfff1 - y0 * ddfff2;
    float dfddfff2 = y0 * f1 - BETA_C * ddfff2;   // ref quirk

    float dfdfdff0 = 10.0f * dfdff1 - 10.0f * dfdff0;
    float dfdfdff1 = j00 * dfdff0 - dfdff1 - y0 * dfdff2;
    float dfdfdff2 = y1 * dfdff0 + y0 * dfdff1 - BETA_C * dfdff2;

    o0 = (f0 + c1 * dff0 + c2 * dfdff0 + c4 * (dfddfff0 + dfdfdff0)) * 0.1f;
    o1 = (f1 + c1 * dff1 + c2 * (ddfff1 + dfdff1)
             + c3 * ddfdfff1 + c4 * (dfddfff1 + dfdfdff1)) * 0.1f;
    o2 = (f2 + c1 * dff2 + c2 * (ddfff2 + dfdff2)
             + c3 * ddfdfff2 + c4 * (dfddfff2 + dfdfdff2)) * 0.1f;
}

// ---- cp.async helpers (LDGSTS) ----
__device__ __forceinline__ void cp16(uint32_t dst_smem, const float4* src) {
    asm volatile("cp.async.ca.shared.global [%0], [%1], 16;"
                 :: "r"(dst_smem), "l"(src) : "memory");
}
__device__ __forceinline__ void cp_commit() {
    asm volatile("cp.async.commit_group;" ::: "memory");
}
__device__ __forceinline__ void cp_wait1() {
    asm volatile("cp.async.wait_group 1;" ::: "memory");
}
__device__ __forceinline__ void cp_wait0() {
    asm volatile("cp.async.wait_group 0;" ::: "memory");
}

// Persistent grid-stride kernel with cp.async double-buffered warp tiles.
// Tile = 768 float4 (1024 triples) per CTA; each warp owns a 96-float4 slice
// of each buffer. Prefetch of tile n+1 (LDGSTS, no registers) overlaps the
// transpose/compute/store of tile n. Warp-autonomous: __syncwarp only.
__global__ void __launch_bounds__(256) IE_LS_kernel(
    const float4* __restrict__ in, float4* __restrict__ out, int n_tiles) {
    __shared__ float4 s[2][768];

    const int lane = threadIdx.x & 31;
    const int warp = threadIdx.x >> 5;

    float4* sw0 = &s[0][warp * 96];
    float4* sw1 = &s[1][warp * 96];
    const uint32_t sa0 = (uint32_t)__cvta_generic_to_shared(sw0 + lane);
    const uint32_t sa1 = (uint32_t)__cvta_generic_to_shared(sw1 + lane);

    int tile = blockIdx.x;
    const int stride = gridDim.x;

    // Prologue: prefetch first tile into buffer 0.
    if (tile < n_tiles) {
        const float4* src = in + (long long)tile * 768 + warp * 96 + lane;
        cp16(sa0,            src);
        cp16(sa0 + 32 * 16,  src + 32);
        cp16(sa0 + 64 * 16,  src + 64);
    }
    cp_commit();

    int buf = 0;
    while (tile < n_tiles) {
        const int next = tile + stride;
        // Prefetch next tile into the other buffer (overlaps this tile's work).
        if (next < n_tiles) {
            const float4* src = in + (long long)next * 768 + warp * 96 + lane;
            const uint32_t d = buf ? sa0 : sa1;
            cp16(d,           src);
            cp16(d + 32 * 16, src + 32);
            cp16(d + 64 * 16, src + 64);
            cp_commit();
            cp_wait1();   // current buffer's group complete; next still in flight
        } else {
            cp_commit();  // empty group keeps the wait count consistent
            cp_wait0();
        }
        __syncwarp();

        float4* sw = buf ? sw1 : sw0;

        // Transpose read: lane owns float4s 3*lane..3*lane+2 (4 triples).
        // 48B-stride LDS.128 is conflict-free; ownership disjoint per lane,
        // so in-place write-back needs no sync.
        float4 a = sw[3 * lane + 0];
        float4 b = sw[3 * lane + 1];
        float4 c = sw[3 * lane + 2];

        float v[12] = {a.x, a.y, a.z, a.w, b.x, b.y, b.z, b.w, c.x, c.y, c.z, c.w};
#pragma unroll
        for (int q = 0; q < 4; q++)
            lorenz_step(v[3 * q + 0], v[3 * q + 1], v[3 * q + 2],
                        v[3 * q + 0], v[3 * q + 1], v[3 * q + 2]);

        sw[3 * lane + 0] = make_float4(v[0], v[1], v[2], v[3]);
        sw[3 * lane + 1] = make_float4(v[4], v[5], v[6], v[7]);
        sw[3 * lane + 2] = make_float4(v[8], v[9], v[10], v[11]);
        __syncwarp();

        // Coalesced store out of this buffer.
        float4* dst = out + (long long)tile * 768 + warp * 96;
        dst[lane]      = sw[lane];
        dst[lane + 32] = sw[lane + 32];
        dst[lane + 64] = sw[lane + 64];
        __syncwarp();   // all lanes done reading before this buffer is re-filled

        buf ^= 1;
        tile = next;
    }
}

// Tail kernel for leftover triples (not hit for the bench shape).
__global__ void IE_LS_tail_kernel(const float* __restrict__ in,
                                  float* __restrict__ out,
                                  int start_triple, int n_triples) {
    int t = start_triple + blockIdx.x * blockDim.x + threadIdx.x;
    if (t >= n_triples) return;
    float o0, o1, o2;
    lorenz_step(in[3 * t], in[3 * t + 1], in[3 * t + 2], o0, o1, o2);
    out[3 * t] = o0; out[3 * t + 1] = o1; out[3 * t + 2] = o2;
}

extern "C" void kernel_launch(void* const* d_in, const int* in_sizes, int n_in,
                              void* d_out, int out_size) {
    const float* in = (const float*)d_in[0];
    float* out = (float*)d_out;
    int n_elems = in_sizes[0];             // 12582912 = 4194304 * 3
    int n_triples = n_elems / 3;
    int n_tiles = n_elems / 3072;          // 3072 floats (1024 triples) per tile

    if (n_tiles > 0) {
        int grid = n_tiles < 1184 ? n_tiles : 1184;   // ~8 CTAs/SM persistent
        IE_LS_kernel<<<grid, 256>>>((const float4*)in, (float4*)out, n_tiles);
    }
    int done = n_tiles * 1024;
    int rem = n_triples - done;
    if (rem > 0) {
        IE_LS_tail_kernel<<<(rem + 255) / 256, 256>>>(in, out, done, n_triples);
    }
}